// round 12
// baseline (speedup 1.0000x reference)
#include <cuda_runtime.h>
#include <cuda_fp16.h>

#define SB   32      // S*B
#define NTOK 2048    // N
#define KK   16      // K
#define DD   32      // D
#define HH   128     // H

#define TPB   256    // threads per block (8 warps)
#define TOKPB 32     // tokens per block (lane = token)
#define NW    8      // warps (warp = 16-h slice)
#define TOTTOK (SB * NTOK)

typedef unsigned long long u64;

// hk[k,h]+b1[h] per (s,b), packed half2. 32*16*64 u32 = 128 KB.
__device__ unsigned g_hkbh[SB * KK * (HH / 2)];
// hx as half2, transposed: g_hxT[h2][global_token]. 64*65536 u32 = 16 MB (L2-resident).
__device__ unsigned g_hxT[(HH / 2) * TOTTOK];

__device__ __forceinline__ u64 pk2(float lo, float hi) {
    u64 r; asm("mov.b64 %0, {%1, %2};" : "=l"(r) : "f"(lo), "f"(hi)); return r;
}
__device__ __forceinline__ void upk2(float& lo, float& hi, u64 v) {
    asm("mov.b64 {%0, %1}, %2;" : "=f"(lo), "=f"(hi) : "l"(v));
}
__device__ __forceinline__ u64 fma2(u64 a, u64 b, u64 c) {
    u64 r; asm("fma.rn.f32x2 %0, %1, %2, %3;" : "=l"(r) : "l"(a), "l"(b), "l"(c)); return r;
}
__device__ __forceinline__ __half2 tanh2(__half2 v) {
    unsigned vi = *reinterpret_cast<unsigned*>(&v), yi;
    asm("tanh.approx.f16x2 %0, %1;" : "=r"(yi) : "r"(vi));
    return *reinterpret_cast<__half2*>(&yi);
}
__device__ __forceinline__ __half2 asH2(unsigned u) { return *reinterpret_cast<__half2*>(&u); }
__device__ __forceinline__ unsigned h2bits(__half2 h) { return *reinterpret_cast<unsigned*>(&h); }

// ---------------------------------------------------------------------------
// Prep: hkbh[sb,k,h/2] = half2( sum_d mu*Wm + tau*Wt + b1 )
// ---------------------------------------------------------------------------
__global__ void prep_kernel(const float* __restrict__ mu,
                            const float* __restrict__ tau,
                            const float* __restrict__ W1,
                            const float* __restrict__ b1) {
    int k  = blockIdx.x;
    int sb = blockIdx.y;
    int t  = threadIdx.x;               // 0..63 -> h pair (2t, 2t+1)
    const float* mur  = mu  + (sb * KK + k) * DD;
    const float* taur = tau + (sb * KK + k) * DD;
    int h0 = 2 * t, h1 = 2 * t + 1;
    float s0 = b1[h0], s1 = b1[h1];
    #pragma unroll
    for (int d = 0; d < DD; d++) {
        float m = mur[d], ta = taur[d];
        s0 = fmaf(m,  W1[(DD     + d) * HH + h0], s0);
        s1 = fmaf(m,  W1[(DD     + d) * HH + h1], s1);
        s0 = fmaf(ta, W1[(2 * DD + d) * HH + h0], s0);
        s1 = fmaf(ta, W1[(2 * DD + d) * HH + h1], s1);
    }
    g_hkbh[(sb * KK + k) * (HH / 2) + t] = h2bits(__floats2half2_rn(s0, s1));
}

// ---------------------------------------------------------------------------
// hx kernel: hxT[h2][tok] = half2( x[tok,:] . Wx[:, 2*h2 .. 2*h2+1] )
// Block = 8 warps x 32 tokens; warp w owns h-slice [16w,16w+16); lane = token.
// f32 FFMA2 accumulation, converted to half2, fully coalesced STG.32.
// ---------------------------------------------------------------------------
__global__ __launch_bounds__(TPB, 4)
void hx_kernel(const float* __restrict__ x,
               const float* __restrict__ W1) {
    __shared__ float xT_s[DD][TOKPB + 1];            // 4.1 KB

    const int tid  = threadIdx.x;
    const int w    = tid >> 5;
    const int lane = tid & 31;                       // token
    const int sb   = blockIdx.y;
    const int tokb = blockIdx.x * TOKPB;
    const int h0   = w * 16;

    // stage x transposed (one step, coalesced LDG.128)
    {
        int tok = tid >> 3, q = tid & 7;             // 32 tok x 8 quads = 256
        float4 v = *reinterpret_cast<const float4*>(
            x + ((size_t)sb * NTOK + tokb + tok) * DD + q * 4);
        xT_s[q * 4 + 0][tok] = v.x; xT_s[q * 4 + 1][tok] = v.y;
        xT_s[q * 4 + 2][tok] = v.z; xT_s[q * 4 + 3][tok] = v.w;
    }
    __syncthreads();

    u64 hx2[8];
    #pragma unroll
    for (int j = 0; j < 8; j++) hx2[j] = 0ull;

    #pragma unroll
    for (int d = 0; d < DD; d++) {
        const ulonglong2* wrow =
            reinterpret_cast<const ulonglong2*>(W1 + d * HH + h0);
        ulonglong2 wa = __ldg(wrow + 0);             // warp-uniform LDG.128
        ulonglong2 wb = __ldg(wrow + 1);
        float xv = xT_s[d][lane];                    // conflict-free LDS.32
        u64 x2 = pk2(xv, xv);
        hx2[0] = fma2(x2, wa.x, hx2[0]);
        hx2[1] = fma2(x2, wa.y, hx2[1]);
        hx2[2] = fma2(x2, wb.x, hx2[2]);
        hx2[3] = fma2(x2, wb.y, hx2[3]);
        const ulonglong2* wrow2 =
            reinterpret_cast<const ulonglong2*>(W1 + d * HH + h0 + 8);
        ulonglong2 wc = __ldg(wrow2 + 0);
        ulonglong2 wd = __ldg(wrow2 + 1);
        hx2[4] = fma2(x2, wc.x, hx2[4]);
        hx2[5] = fma2(x2, wc.y, hx2[5]);
        hx2[6] = fma2(x2, wd.x, hx2[6]);
        hx2[7] = fma2(x2, wd.y, hx2[7]);
    }

    const int gtok = sb * NTOK + tokb + lane;
    #pragma unroll
    for (int q = 0; q < 8; q++) {
        float lo, hi;
        upk2(lo, hi, hx2[q]);
        // row h2 = w*8+q, col gtok: lanes -> consecutive cols, coalesced STG.32
        g_hxT[(size_t)(w * 8 + q) * TOTTOK + gtok] = h2bits(__floats2half2_rn(lo, hi));
    }
}

// ---------------------------------------------------------------------------
// Main: pure tanh sweep. Block = 8 warps x 32 tokens; warp w = 16-h slice;
// lane = token. hx loaded (coalesced) from g_hxT; inner loop all-f16:
//   HADD2 -> tanh.f16x2 -> HFMA2; per-(k) partial stored as half2 u32.
// Reduce converts to f32 and softmaxes.
// ---------------------------------------------------------------------------
__global__ __launch_bounds__(TPB, 5)
void main_kernel(const float* __restrict__ W2,
                 float* __restrict__ out) {
    __shared__ unsigned hkb_s[KK * (HH / 2)];        //  4 KB
    __shared__ unsigned part_s[NW][TOKPB][KK + 1];   // 17.4 KB (stride-17 rows)

    const int tid  = threadIdx.x;
    const int w    = tid >> 5;
    const int lane = tid & 31;                       // token
    const int sb   = blockIdx.y;
    const int tokb = blockIdx.x * TOKPB;
    const int h0   = w * 16;
    const int gtok = sb * NTOK + tokb + lane;

    for (int i = tid; i < KK * (HH / 2); i += TPB)
        hkb_s[i] = g_hkbh[sb * KK * (HH / 2) + i];

    // hx slice: 8 coalesced LDG.32 (L2-resident producer output)
    unsigned hxh[8];
    #pragma unroll
    for (int q = 0; q < 8; q++)
        hxh[q] = g_hxT[(size_t)(w * 8 + q) * TOTTOK + gtok];

    // W2 slice as half2 (warp-uniform LDG)
    __half2 w2h[8];
    {
        const float4* w2p = reinterpret_cast<const float4*>(W2 + h0);
        #pragma unroll
        for (int q = 0; q < 4; q++) {
            float4 wv = __ldg(w2p + q);
            w2h[2 * q + 0] = __floats2half2_rn(wv.x, wv.y);
            w2h[2 * q + 1] = __floats2half2_rn(wv.z, wv.w);
        }
    }
    __syncthreads();

    // ---- tanh sweep: all-f16, partial (even,odd) kept as one half2 ----
    #pragma unroll
    for (int k = 0; k < KK; k++) {
        const uint4* hkp = reinterpret_cast<const uint4*>(&hkb_s[k * (HH / 2) + w * 8]);
        uint4 hA = hkp[0], hB = hkp[1];              // warp-uniform LDS.128
        __half2 a0, a1, a2, a3;
        a0 = __hmul2(tanh2(__hadd2(asH2(hxh[0]), asH2(hA.x))), w2h[0]);
        a1 = __hmul2(tanh2(__hadd2(asH2(hxh[1]), asH2(hA.y))), w2h[1]);
        a2 = __hmul2(tanh2(__hadd2(asH2(hxh[2]), asH2(hA.z))), w2h[2]);
        a3 = __hmul2(tanh2(__hadd2(asH2(hxh[3]), asH2(hA.w))), w2h[3]);
        a0 = __hfma2(tanh2(__hadd2(asH2(hxh[4]), asH2(hB.x))), w2h[4], a0);
        a1 = __hfma2(tanh2(__hadd2(asH2(hxh[5]), asH2(hB.y))), w2h[5], a1);
        a2 = __hfma2(tanh2(__hadd2(asH2(hxh[6]), asH2(hB.z))), w2h[6], a2);
        a3 = __hfma2(tanh2(__hadd2(asH2(hxh[7]), asH2(hB.w))), w2h[7], a3);
        __half2 a = __hadd2(__hadd2(a0, a1), __hadd2(a2, a3));
        part_s[w][lane][k] = h2bits(a);              // stride-17: conflict-free
    }
    __syncthreads();

    // ---- Reduce + softmax: thread = (token = tid>>3, k-pair = tid&7) ----
    const int tok = tid >> 3;
    const int kp  = tid & 7;
    float g0 = 0.f, g1 = 0.f;
    #pragma unroll
    for (int ww = 0; ww < NW; ww++) {
        float2 f0 = __half22float2(asH2(part_s[ww][tok][2 * kp + 0]));
        float2 f1 = __half22float2(asH2(part_s[ww][tok][2 * kp + 1]));
        g0 += f0.x + f0.y;
        g1 += f1.x + f1.y;
    }

    float m = fmaxf(g0, g1);
    m = fmaxf(m, __shfl_xor_sync(0xffffffffu, m, 1));
    m = fmaxf(m, __shfl_xor_sync(0xffffffffu, m, 2));
    m = fmaxf(m, __shfl_xor_sync(0xffffffffu, m, 4));

    float e0 = __expf(g0 - m), e1 = __expf(g1 - m);
    float s = e0 + e1;
    s += __shfl_xor_sync(0xffffffffu, s, 1);
    s += __shfl_xor_sync(0xffffffffu, s, 2);
    s += __shfl_xor_sync(0xffffffffu, s, 4);
    float inv = __fdividef(1.f, s);

    float2 o;
    o.x = e0 * inv; o.y = e1 * inv;
    reinterpret_cast<float2*>(out + ((size_t)sb * NTOK + tokb + tok) * KK)[kp] = o;
}

extern "C" void kernel_launch(void* const* d_in, const int* in_sizes, int n_in,
                              void* d_out, int out_size) {
    const float* x   = (const float*)d_in[0];
    const float* mu  = (const float*)d_in[1];
    const float* tau = (const float*)d_in[2];
    const float* W1  = (const float*)d_in[3];
    const float* b1  = (const float*)d_in[4];
    const float* W2  = (const float*)d_in[5];
    // d_in[6] = b2: cancels in softmax, unused.
    float* out = (float*)d_out;

    prep_kernel<<<dim3(KK, SB), HH / 2>>>(mu, tau, W1, b1);
    hx_kernel<<<dim3(NTOK / TOKPB, SB), TPB>>>(x, W1);
    main_kernel<<<dim3(NTOK / TOKPB, SB), TPB>>>(W2, out);
}

// round 13
// speedup vs baseline: 1.6362x; 1.6362x over previous
#include <cuda_runtime.h>
#include <cuda_fp16.h>

#define SB   32      // S*B
#define NTOK 2048    // N
#define KK   16      // K
#define DD   32      // D
#define HH   128     // H

#define TPB   256    // threads per block (8 warps)
#define TOKPB 64     // tokens per block
#define NW    8      // warps (warp = 16-h slice)
#define TT    2      // token-groups per thread
#define XROW  36     // padded x row (floats): 144B, 16B-aligned, odd 8B-granule stride

typedef unsigned long long u64;

// hk[k,h]+b1[h] per (s,b), packed half2. 32*16*64 u32 = 128 KB.
__device__ unsigned g_hkbh[SB * KK * (HH / 2)];

__device__ __forceinline__ u64 pk2(float lo, float hi) {
    u64 r; asm("mov.b64 %0, {%1, %2};" : "=l"(r) : "f"(lo), "f"(hi)); return r;
}
__device__ __forceinline__ void upk2(float& lo, float& hi, u64 v) {
    asm("mov.b64 {%0, %1}, %2;" : "=f"(lo), "=f"(hi) : "l"(v));
}
__device__ __forceinline__ u64 fma2(u64 a, u64 b, u64 c) {
    u64 r; asm("fma.rn.f32x2 %0, %1, %2, %3;" : "=l"(r) : "l"(a), "l"(b), "l"(c)); return r;
}
__device__ __forceinline__ __half2 tanh2(__half2 v) {
    unsigned vi = *reinterpret_cast<unsigned*>(&v), yi;
    asm("tanh.approx.f16x2 %0, %1;" : "=r"(yi) : "r"(vi));
    return *reinterpret_cast<__half2*>(&yi);
}
__device__ __forceinline__ __half2 asH2(unsigned u) { return *reinterpret_cast<__half2*>(&u); }
__device__ __forceinline__ unsigned h2bits(__half2 h) { return *reinterpret_cast<unsigned*>(&h); }

// ---------------------------------------------------------------------------
// Prep: hkbh[sb,k,h/2] = half2( sum_d mu*Wm + tau*Wt + b1 )
// 256-thread blocks, 4 k's per block: grid (4, SB) = 128 blocks.
// ---------------------------------------------------------------------------
__global__ __launch_bounds__(TPB)
void prep_kernel(const float* __restrict__ mu,
                 const float* __restrict__ tau,
                 const float* __restrict__ W1,
                 const float* __restrict__ b1) {
    int sb = blockIdx.y;
    int k  = blockIdx.x * 4 + (threadIdx.x >> 6);   // 4 k per block
    int hp = threadIdx.x & 63;                       // h pair (2hp, 2hp+1)
    const float* mur  = mu  + (sb * KK + k) * DD;
    const float* taur = tau + (sb * KK + k) * DD;
    float2 b = *reinterpret_cast<const float2*>(b1 + 2 * hp);
    float s0 = b.x, s1 = b.y;
    #pragma unroll
    for (int d = 0; d < DD; d++) {
        float m = mur[d], ta = taur[d];              // warp-uniform LDG
        float2 wm = __ldg(reinterpret_cast<const float2*>(W1 + (DD     + d) * HH + 2 * hp));
        float2 wt = __ldg(reinterpret_cast<const float2*>(W1 + (2 * DD + d) * HH + 2 * hp));
        s0 = fmaf(m, wm.x, s0);  s1 = fmaf(m, wm.y, s1);
        s0 = fmaf(ta, wt.x, s0); s1 = fmaf(ta, wt.y, s1);
    }
    g_hkbh[(sb * KK + k) * (HH / 2) + hp] = h2bits(__floats2half2_rn(s0, s1));
}

// ---------------------------------------------------------------------------
// Main (R10 structure + micro-opts): block = 8 warps x 64 tokens; warp w owns
// h-slice [16w,16w+16); thread register-blocks TT=2 token groups.
//   Phase A: f32 FFMA2, x read as float2 d-pairs from padded [tok][36] rows.
//   Phase B: all-f16 inner loop; (k,t) partial kept as ONE half2 -> STS.32.
// One sync, then f32 reduce + softmax.
// ---------------------------------------------------------------------------
__global__ __launch_bounds__(TPB, 3)
void main_kernel(const float* __restrict__ x,
                 const float* __restrict__ W1,
                 const float* __restrict__ W2,
                 float* __restrict__ out) {
    __shared__ unsigned hkb_s[KK * (HH / 2)];        //  4 KB
    __shared__ float    x_s[TOKPB][XROW];            //  9 KB (row 144B)
    __shared__ unsigned part_s[NW][TOKPB][KK + 1];   // 17.4 KB (stride-17 rows)

    const int tid  = threadIdx.x;
    const int w    = tid >> 5;                       // warp id = h-slice
    const int lane = tid & 31;
    const int sb   = blockIdx.y;
    const int tokb = blockIdx.x * TOKPB;
    const int h0   = w * 16;

    for (int i = tid; i < KK * (HH / 2); i += TPB)
        hkb_s[i] = g_hkbh[sb * KK * (HH / 2) + i];

    // Stage x: x_s[tok][d] with 36-float rows (coalesced LDG.128)
    #pragma unroll
    for (int it = 0; it < 2; it++) {
        int idx = tid + it * TPB;                    // 0..511 = 64 tok x 8 quads
        int tok = idx >> 3, q = idx & 7;
        float4 v = *reinterpret_cast<const float4*>(
            x + ((size_t)sb * NTOK + tokb + tok) * DD + q * 4);
        *reinterpret_cast<float4*>(&x_s[tok][q * 4]) = v;
    }
    __syncthreads();

    // ---- Phase A: hx (f32, FFMA2), d processed in pairs via LDS.64 ----
    u64 hx2[TT][8];
    #pragma unroll
    for (int t = 0; t < TT; t++)
        #pragma unroll
        for (int j = 0; j < 8; j++) hx2[t][j] = 0ull;

    #pragma unroll
    for (int d2 = 0; d2 < DD / 2; d2++) {
        const int d0 = 2 * d2;
        const ulonglong2* wr0 = reinterpret_cast<const ulonglong2*>(W1 + d0 * HH + h0);
        const ulonglong2* wr1 = reinterpret_cast<const ulonglong2*>(W1 + (d0 + 1) * HH + h0);
        ulonglong2 wa0 = __ldg(wr0 + 0), wb0 = __ldg(wr0 + 1);   // warp-uniform LDG.128
        ulonglong2 wa1 = __ldg(wr1 + 0), wb1 = __ldg(wr1 + 1);
        #pragma unroll
        for (int t = 0; t < TT; t++) {
            float2 xv = *reinterpret_cast<const float2*>(&x_s[t * 32 + lane][d0]);
            u64 x20 = pk2(xv.x, xv.x);
            u64 x21 = pk2(xv.y, xv.y);
            hx2[t][0] = fma2(x20, wa0.x, hx2[t][0]);
            hx2[t][1] = fma2(x20, wa0.y, hx2[t][1]);
            hx2[t][2] = fma2(x20, wb0.x, hx2[t][2]);
            hx2[t][3] = fma2(x20, wb0.y, hx2[t][3]);
            hx2[t][0] = fma2(x21, wa1.x, hx2[t][0]);
            hx2[t][1] = fma2(x21, wa1.y, hx2[t][1]);
            hx2[t][2] = fma2(x21, wb1.x, hx2[t][2]);
            hx2[t][3] = fma2(x21, wb1.y, hx2[t][3]);
        }
        const ulonglong2* wr0b = reinterpret_cast<const ulonglong2*>(W1 + d0 * HH + h0 + 8);
        const ulonglong2* wr1b = reinterpret_cast<const ulonglong2*>(W1 + (d0 + 1) * HH + h0 + 8);
        ulonglong2 wc0 = __ldg(wr0b + 0), wd0 = __ldg(wr0b + 1);
        ulonglong2 wc1 = __ldg(wr1b + 0), wd1 = __ldg(wr1b + 1);
        #pragma unroll
        for (int t = 0; t < TT; t++) {
            float2 xv = *reinterpret_cast<const float2*>(&x_s[t * 32 + lane][d0]);
            u64 x20 = pk2(xv.x, xv.x);
            u64 x21 = pk2(xv.y, xv.y);
            hx2[t][4] = fma2(x20, wc0.x, hx2[t][4]);
            hx2[t][5] = fma2(x20, wc0.y, hx2[t][5]);
            hx2[t][6] = fma2(x20, wd0.x, hx2[t][6]);
            hx2[t][7] = fma2(x20, wd0.y, hx2[t][7]);
            hx2[t][4] = fma2(x21, wc1.x, hx2[t][4]);
            hx2[t][5] = fma2(x21, wc1.y, hx2[t][5]);
            hx2[t][6] = fma2(x21, wd1.x, hx2[t][6]);
            hx2[t][7] = fma2(x21, wd1.y, hx2[t][7]);
        }
    }

    // One-time hx -> half2
    unsigned hxh[TT][8];
    #pragma unroll
    for (int t = 0; t < TT; t++)
        #pragma unroll
        for (int q = 0; q < 8; q++) {
            float lo, hi;
            upk2(lo, hi, hx2[t][q]);
            hxh[t][q] = h2bits(__floats2half2_rn(lo, hi));
        }

    // W2 slice as half2 (warp-uniform LDG)
    __half2 w2h[8];
    {
        const float4* w2p = reinterpret_cast<const float4*>(W2 + h0);
        #pragma unroll
        for (int q = 0; q < 4; q++) {
            float4 wv = __ldg(w2p + q);
            w2h[2 * q + 0] = __floats2half2_rn(wv.x, wv.y);
            w2h[2 * q + 1] = __floats2half2_rn(wv.z, wv.w);
        }
    }

    // ---- Phase B: all-f16 inner loop, half2 partial straight to smem ----
    #pragma unroll
    for (int k = 0; k < KK; k++) {
        const uint4* hkp = reinterpret_cast<const uint4*>(&hkb_s[k * (HH / 2) + w * 8]);
        uint4 hA = hkp[0], hB = hkp[1];              // warp-uniform LDS.128
        #pragma unroll
        for (int t = 0; t < TT; t++) {
            __half2 a0, a1, a2, a3;
            a0 = __hmul2(tanh2(__hadd2(asH2(hxh[t][0]), asH2(hA.x))), w2h[0]);
            a1 = __hmul2(tanh2(__hadd2(asH2(hxh[t][1]), asH2(hA.y))), w2h[1]);
            a2 = __hmul2(tanh2(__hadd2(asH2(hxh[t][2]), asH2(hA.z))), w2h[2]);
            a3 = __hmul2(tanh2(__hadd2(asH2(hxh[t][3]), asH2(hA.w))), w2h[3]);
            a0 = __hfma2(tanh2(__hadd2(asH2(hxh[t][4]), asH2(hB.x))), w2h[4], a0);
            a1 = __hfma2(tanh2(__hadd2(asH2(hxh[t][5]), asH2(hB.y))), w2h[5], a1);
            a2 = __hfma2(tanh2(__hadd2(asH2(hxh[t][6]), asH2(hB.z))), w2h[6], a2);
            a3 = __hfma2(tanh2(__hadd2(asH2(hxh[t][7]), asH2(hB.w))), w2h[7], a3);
            __half2 a = __hadd2(__hadd2(a0, a1), __hadd2(a2, a3));
            part_s[w][t * 32 + lane][k] = h2bits(a); // stride-17: conflict-free
        }
    }
    __syncthreads();

    // ---- Reduce (f32) + softmax: thread = (token = tid>>2, k-quad = tid&3) ----
    const int tok = tid >> 2;
    const int kq  = tid & 3;
    float g[4];
    #pragma unroll
    for (int j = 0; j < 4; j++) {
        int k = 4 * kq + j;
        float s = 0.f;
        #pragma unroll
        for (int ww = 0; ww < NW; ww++) {
            float2 f = __half22float2(asH2(part_s[ww][tok][k]));
            s += f.x + f.y;
        }
        g[j] = s;
    }

    float m = fmaxf(fmaxf(g[0], g[1]), fmaxf(g[2], g[3]));
    m = fmaxf(m, __shfl_xor_sync(0xffffffffu, m, 1));
    m = fmaxf(m, __shfl_xor_sync(0xffffffffu, m, 2));

    float e0 = __expf(g[0] - m), e1 = __expf(g[1] - m);
    float e2 = __expf(g[2] - m), e3 = __expf(g[3] - m);
    float s = (e0 + e1) + (e2 + e3);
    s += __shfl_xor_sync(0xffffffffu, s, 1);
    s += __shfl_xor_sync(0xffffffffu, s, 2);
    float inv = __fdividef(1.f, s);

    float4 o;
    o.x = e0 * inv; o.y = e1 * inv; o.z = e2 * inv; o.w = e3 * inv;
    reinterpret_cast<float4*>(out + ((size_t)sb * NTOK + tokb + tok) * KK)[kq] = o;
}

extern "C" void kernel_launch(void* const* d_in, const int* in_sizes, int n_in,
                              void* d_out, int out_size) {
    const float* x   = (const float*)d_in[0];
    const float* mu  = (const float*)d_in[1];
    const float* tau = (const float*)d_in[2];
    const float* W1  = (const float*)d_in[3];
    const float* b1  = (const float*)d_in[4];
    const float* W2  = (const float*)d_in[5];
    // d_in[6] = b2: cancels in softmax, unused.
    float* out = (float*)d_out;

    prep_kernel<<<dim3(KK / 4, SB), TPB>>>(mu, tau, W1, b1);
    main_kernel<<<dim3(NTOK / TOKPB, SB), TPB>>>(x, W1, W2, out);
}

// round 14
// speedup vs baseline: 1.8197x; 1.1122x over previous
#include <cuda_runtime.h>
#include <cuda_fp16.h>

#define SB   32      // S*B
#define NTOK 2048    // N
#define KK   16      // K
#define DD   32      // D
#define HH   128     // H

#define TPB   256    // threads per block (8 warps)
#define TOKPB 64     // tokens per block
#define NW    8      // warps (warp = 16-h slice)
#define TT    2      // token-groups per thread

#define XLD   40     // x_s row stride (halfs): 80B = 5 granules (odd) -> conflict-free
#define WLD   136    // W_s row stride (halfs): 272B = 17 granules (odd)
#define HXP   11     // hx16 row stride (u32): lane*11 mod 64 distinct
#define PRT   17     // part_s row stride (u32)

// smem overlay offsets (bytes)
#define HKB_OFF  0                         // 4096 B
#define X_OFF    4096                      // 64*40*2  = 5120 B
#define W_OFF    (X_OFF + 5120)            // 32*136*2 = 8704 B  (end 17920)
#define HX_OFF   17920                     // 8*64*11*4 = 22528 B (end 40448)
#define PART_OFF 4096                      // 8*64*17*4 = 34816 B (end 38912; overlays x/W/hx after they die)
#define SMEM_TOTAL 40448

typedef unsigned long long u64;

// hk[k,h]+b1[h] per (s,b), packed half2. 32*16*64 u32 = 128 KB.
__device__ unsigned g_hkbh[SB * KK * (HH / 2)];

__device__ __forceinline__ __half2 tanh2(__half2 v) {
    unsigned vi = *reinterpret_cast<unsigned*>(&v), yi;
    asm("tanh.approx.f16x2 %0, %1;" : "=r"(yi) : "r"(vi));
    return *reinterpret_cast<__half2*>(&yi);
}
__device__ __forceinline__ __half2 asH2(unsigned u) { return *reinterpret_cast<__half2*>(&u); }
__device__ __forceinline__ unsigned h2bits(__half2 h) { return *reinterpret_cast<unsigned*>(&h); }
__device__ __forceinline__ unsigned smem_u32(const void* p) {
    return (unsigned)__cvta_generic_to_shared(p);
}

// ---------------------------------------------------------------------------
// Prep: hkbh[sb,k,h/2] = half2( sum_d mu*Wm + tau*Wt + b1 )  (R13 version)
// ---------------------------------------------------------------------------
__global__ __launch_bounds__(TPB)
void prep_kernel(const float* __restrict__ mu,
                 const float* __restrict__ tau,
                 const float* __restrict__ W1,
                 const float* __restrict__ b1) {
    int sb = blockIdx.y;
    int k  = blockIdx.x * 4 + (threadIdx.x >> 6);
    int hp = threadIdx.x & 63;
    const float* mur  = mu  + (sb * KK + k) * DD;
    const float* taur = tau + (sb * KK + k) * DD;
    float2 b = *reinterpret_cast<const float2*>(b1 + 2 * hp);
    float s0 = b.x, s1 = b.y;
    #pragma unroll
    for (int d = 0; d < DD; d++) {
        float m = mur[d], ta = taur[d];
        float2 wm = __ldg(reinterpret_cast<const float2*>(W1 + (DD     + d) * HH + 2 * hp));
        float2 wt = __ldg(reinterpret_cast<const float2*>(W1 + (2 * DD + d) * HH + 2 * hp));
        s0 = fmaf(m, wm.x, s0);  s1 = fmaf(m, wm.y, s1);
        s0 = fmaf(ta, wt.x, s0); s1 = fmaf(ta, wt.y, s1);
    }
    g_hkbh[(sb * KK + k) * (HH / 2) + hp] = h2bits(__floats2half2_rn(s0, s1));
}

// ---------------------------------------------------------------------------
// Main: phase A = tensor-core GEMM hx[64 tok x 128 h] via mma.m16n8k16
// (warp w owns n-tiles 2w, 2w+1 = its 16-h slice). Epilogue drops half2
// h-pairs straight into hx16. Phase B / reduce / softmax = R13.
// ---------------------------------------------------------------------------
__global__ __launch_bounds__(TPB, 3)
void main_kernel(const float* __restrict__ x,
                 const float* __restrict__ W1,
                 const float* __restrict__ W2,
                 float* __restrict__ out) {
    __shared__ __align__(16) unsigned char smraw[SMEM_TOTAL];
    unsigned* hkb_s  = reinterpret_cast<unsigned*>(smraw + HKB_OFF);
    __half*   x_s    = reinterpret_cast<__half*>(smraw + X_OFF);
    __half*   W_s    = reinterpret_cast<__half*>(smraw + W_OFF);
    unsigned* hx_s   = reinterpret_cast<unsigned*>(smraw + HX_OFF);
    unsigned* part_s = reinterpret_cast<unsigned*>(smraw + PART_OFF);

    const int tid  = threadIdx.x;
    const int w    = tid >> 5;
    const int lane = tid & 31;
    const int sb   = blockIdx.y;
    const int tokb = blockIdx.x * TOKPB;
    const int h0   = w * 16;

    for (int i = tid; i < KK * (HH / 2); i += TPB)
        hkb_s[i] = g_hkbh[sb * KK * (HH / 2) + i];

    // Stage x as f16: x_s[tok][d], row stride XLD
    #pragma unroll
    for (int it = 0; it < 2; it++) {
        int idx = tid + it * TPB;                    // 64 tok x 8 quads
        int tok = idx >> 3, q = idx & 7;
        float4 v = *reinterpret_cast<const float4*>(
            x + ((size_t)sb * NTOK + tokb + tok) * DD + q * 4);
        unsigned* p = reinterpret_cast<unsigned*>(x_s + tok * XLD + q * 4);
        p[0] = h2bits(__floats2half2_rn(v.x, v.y));
        p[1] = h2bits(__floats2half2_rn(v.z, v.w));
    }
    // Stage Wx (rows 0..31 of W1) as f16: W_s[k][n], row stride WLD
    #pragma unroll
    for (int it = 0; it < 8; it++) {
        int idx = tid + it * TPB;                    // 2048 half2
        int k = idx >> 6, n2 = idx & 63;
        float2 wv = __ldg(reinterpret_cast<const float2*>(W1 + k * HH + n2 * 2));
        reinterpret_cast<unsigned*>(W_s + k * WLD)[n2] = h2bits(__floats2half2_rn(wv.x, wv.y));
    }
    __syncthreads();

    // ---- Phase A: mma.m16n8k16 row.col f32 acc ----
    const unsigned xb = smem_u32(x_s);
    const unsigned wb = smem_u32(W_s);
    float c[4][2][4];
    #pragma unroll
    for (int mt = 0; mt < 4; mt++)
        #pragma unroll
        for (int nt = 0; nt < 2; nt++)
            #pragma unroll
            for (int r = 0; r < 4; r++) c[mt][nt][r] = 0.f;

    #pragma unroll
    for (int kh = 0; kh < 2; kh++) {
        // B frags: k = kh*16 + (lane&15), n = h0 + nt*8 (x2.trans, lanes 0-15)
        unsigned b0[2], b1[2];
        #pragma unroll
        for (int nt = 0; nt < 2; nt++) {
            unsigned addrB = wb + ((kh * 16 + (lane & 15)) * WLD + h0 + nt * 8) * 2;
            asm volatile("ldmatrix.sync.aligned.m8n8.x2.trans.shared.b16 {%0,%1}, [%2];"
                         : "=r"(b0[nt]), "=r"(b1[nt]) : "r"(addrB));
        }
        #pragma unroll
        for (int mt = 0; mt < 4; mt++) {
            int mA = mt * 16 + (lane & 7) + ((lane & 8) ? 8 : 0);
            int kA = kh * 16 + ((lane & 16) ? 8 : 0);
            unsigned addrA = xb + (mA * XLD + kA) * 2;
            unsigned a0, a1, a2, a3;
            asm volatile("ldmatrix.sync.aligned.m8n8.x4.shared.b16 {%0,%1,%2,%3}, [%4];"
                         : "=r"(a0), "=r"(a1), "=r"(a2), "=r"(a3) : "r"(addrA));
            #pragma unroll
            for (int nt = 0; nt < 2; nt++) {
                asm volatile(
                    "mma.sync.aligned.m16n8k16.row.col.f32.f16.f16.f32 "
                    "{%0,%1,%2,%3}, {%4,%5,%6,%7}, {%8,%9}, {%0,%1,%2,%3};"
                    : "+f"(c[mt][nt][0]), "+f"(c[mt][nt][1]),
                      "+f"(c[mt][nt][2]), "+f"(c[mt][nt][3])
                    : "r"(a0), "r"(a1), "r"(a2), "r"(a3),
                      "r"(b0[nt]), "r"(b1[nt]));
            }
        }
    }

    // Epilogue: D frag (c0,c1)=(row g, cols 2j,2j+1) -> one half2 per STS.32
    {
        const int g = lane >> 2, j = lane & 3;
        #pragma unroll
        for (int mt = 0; mt < 4; mt++)
            #pragma unroll
            for (int nt = 0; nt < 2; nt++) {
                int col = nt * 4 + j;
                hx_s[(w * 64 + mt * 16 + g)     * HXP + col] =
                    h2bits(__floats2half2_rn(c[mt][nt][0], c[mt][nt][1]));
                hx_s[(w * 64 + mt * 16 + g + 8) * HXP + col] =
                    h2bits(__floats2half2_rn(c[mt][nt][2], c[mt][nt][3]));
            }
    }
    __syncthreads();

    // Pull this thread's hx (lane's tokens, warp's h-slice) into registers
    unsigned hxh[TT][8];
    #pragma unroll
    for (int t = 0; t < TT; t++)
        #pragma unroll
        for (int q = 0; q < 8; q++)
            hxh[t][q] = hx_s[(w * 64 + t * 32 + lane) * HXP + q];
    __syncthreads();   // hx16 region is dead; part_s overlay may now be written

    // W2 slice as half2 (warp-uniform LDG)
    __half2 w2h[8];
    {
        const float4* w2p = reinterpret_cast<const float4*>(W2 + h0);
        #pragma unroll
        for (int q = 0; q < 4; q++) {
            float4 wv = __ldg(w2p + q);
            w2h[2 * q + 0] = __floats2half2_rn(wv.x, wv.y);
            w2h[2 * q + 1] = __floats2half2_rn(wv.z, wv.w);
        }
    }

    // ---- Phase B: all-f16 inner loop, half2 partial straight to smem ----
    #pragma unroll
    for (int k = 0; k < KK; k++) {
        const uint4* hkp = reinterpret_cast<const uint4*>(&hkb_s[k * (HH / 2) + w * 8]);
        uint4 hA = hkp[0], hB = hkp[1];              // warp-uniform LDS.128
        #pragma unroll
        for (int t = 0; t < TT; t++) {
            __half2 a0, a1, a2, a3;
            a0 = __hmul2(tanh2(__hadd2(asH2(hxh[t][0]), asH2(hA.x))), w2h[0]);
            a1 = __hmul2(tanh2(__hadd2(asH2(hxh[t][1]), asH2(hA.y))), w2h[1]);
            a2 = __hmul2(tanh2(__hadd2(asH2(hxh[t][2]), asH2(hA.z))), w2h[2]);
            a3 = __hmul2(tanh2(__hadd2(asH2(hxh[t][3]), asH2(hA.w))), w2h[3]);
            a0 = __hfma2(tanh2(__hadd2(asH2(hxh[t][4]), asH2(hB.x))), w2h[4], a0);
            a1 = __hfma2(tanh2(__hadd2(asH2(hxh[t][5]), asH2(hB.y))), w2h[5], a1);
            a2 = __hfma2(tanh2(__hadd2(asH2(hxh[t][6]), asH2(hB.z))), w2h[6], a2);
            a3 = __hfma2(tanh2(__hadd2(asH2(hxh[t][7]), asH2(hB.w))), w2h[7], a3);
            __half2 a = __hadd2(__hadd2(a0, a1), __hadd2(a2, a3));
            part_s[(w * 64 + t * 32 + lane) * PRT + k] = h2bits(a);
        }
    }
    __syncthreads();

    // ---- Reduce (f32) + softmax: thread = (token = tid>>2, k-quad = tid&3) ----
    const int tok = tid >> 2;
    const int kq  = tid & 3;
    float g[4];
    #pragma unroll
    for (int j = 0; j < 4; j++) {
        int k = 4 * kq + j;
        float s = 0.f;
        #pragma unroll
        for (int ww = 0; ww < NW; ww++) {
            float2 f = __half22float2(asH2(part_s[(ww * 64 + tok) * PRT + k]));
            s += f.x + f.y;
        }
        g[j] = s;
    }

    float m = fmaxf(fmaxf(g[0], g[1]), fmaxf(g[2], g[3]));
    m = fmaxf(m, __shfl_xor_sync(0xffffffffu, m, 1));
    m = fmaxf(m, __shfl_xor_sync(0xffffffffu, m, 2));

    float e0 = __expf(g[0] - m), e1 = __expf(g[1] - m);
    float e2 = __expf(g[2] - m), e3 = __expf(g[3] - m);
    float s = (e0 + e1) + (e2 + e3);
    s += __shfl_xor_sync(0xffffffffu, s, 1);
    s += __shfl_xor_sync(0xffffffffu, s, 2);
    float inv = __fdividef(1.f, s);

    float4 o;
    o.x = e0 * inv; o.y = e1 * inv; o.z = e2 * inv; o.w = e3 * inv;
    reinterpret_cast<float4*>(out + ((size_t)sb * NTOK + tokb + tok) * KK)[kq] = o;
}

extern "C" void kernel_launch(void* const* d_in, const int* in_sizes, int n_in,
                              void* d_out, int out_size) {
    const float* x   = (const float*)d_in[0];
    const float* mu  = (const float*)d_in[1];
    const float* tau = (const float*)d_in[2];
    const float* W1  = (const float*)d_in[3];
    const float* b1  = (const float*)d_in[4];
    const float* W2  = (const float*)d_in[5];
    // d_in[6] = b2: cancels in softmax, unused.
    float* out = (float*)d_out;

    prep_kernel<<<dim3(KK / 4, SB), TPB>>>(mu, tau, W1, b1);
    main_kernel<<<dim3(NTOK / TOKPB, SB), TPB>>>(x, W1, W2, out);
}

// round 15
// speedup vs baseline: 1.8773x; 1.0316x over previous
#include <cuda_runtime.h>
#include <cuda_fp16.h>

#define SB   32      // S*B
#define NTOK 2048    // N
#define KK   16      // K
#define DD   32      // D
#define HH   128     // H

#define TPB   256    // threads per block (8 warps)
#define TOKPB 64     // tokens per block
#define NW    8      // warps (warp = 16-h slice)
#define TT    2      // token-groups per thread

#define XLD   40     // x_s row stride (halfs): 80B, odd 8B-granule stride
#define WLD   136    // W_s row stride (halfs): 272B
#define HXP   11     // hx16 row stride (u32)
#define PRT   17     // part_s row stride (u32)

// smem overlay offsets (bytes)
#define HKB_OFF  0                         // 4096 B
#define X_OFF    4096                      // 64*40*2  = 5120 B
#define W_OFF    (X_OFF + 5120)            // 32*136*2 = 8704 B  (end 17920)
#define HX_OFF   17920                     // 8*64*11*4 = 22528 B (end 40448)
#define PART_OFF 4096                      // 8*64*17*4 = 34816 B (end 38912)
#define SMEM_TOTAL 40448

typedef unsigned long long u64;

// hk[k,h]+b1[h] per (s,b), packed half2. 32*16*64 u32 = 128 KB.
__device__ unsigned g_hkbh[SB * KK * (HH / 2)];

__device__ __forceinline__ __half2 tanh2(__half2 v) {
    unsigned vi = *reinterpret_cast<unsigned*>(&v), yi;
    asm("tanh.approx.f16x2 %0, %1;" : "=r"(yi) : "r"(vi));
    return *reinterpret_cast<__half2*>(&yi);
}
__device__ __forceinline__ __half2 asH2(unsigned u) { return *reinterpret_cast<__half2*>(&u); }
__device__ __forceinline__ unsigned h2bits(__half2 h) { return *reinterpret_cast<unsigned*>(&h); }
__device__ __forceinline__ unsigned smem_u32(const void* p) {
    return (unsigned)__cvta_generic_to_shared(p);
}

// ---------------------------------------------------------------------------
// Prep: hkbh[sb,k,h/2] = half2( sum_d mu*Wm + tau*Wt + b1 )
// ---------------------------------------------------------------------------
__global__ __launch_bounds__(TPB)
void prep_kernel(const float* __restrict__ mu,
                 const float* __restrict__ tau,
                 const float* __restrict__ W1,
                 const float* __restrict__ b1) {
    int sb = blockIdx.y;
    int k  = blockIdx.x * 4 + (threadIdx.x >> 6);
    int hp = threadIdx.x & 63;
    const float* mur  = mu  + (sb * KK + k) * DD;
    const float* taur = tau + (sb * KK + k) * DD;
    float2 b = *reinterpret_cast<const float2*>(b1 + 2 * hp);
    float s0 = b.x, s1 = b.y;
    #pragma unroll
    for (int d = 0; d < DD; d++) {
        float m = mur[d], ta = taur[d];
        float2 wm = __ldg(reinterpret_cast<const float2*>(W1 + (DD     + d) * HH + 2 * hp));
        float2 wt = __ldg(reinterpret_cast<const float2*>(W1 + (2 * DD + d) * HH + 2 * hp));
        s0 = fmaf(m, wm.x, s0);  s1 = fmaf(m, wm.y, s1);
        s0 = fmaf(ta, wt.x, s0); s1 = fmaf(ta, wt.y, s1);
    }
    g_hkbh[(sb * KK + k) * (HH / 2) + hp] = h2bits(__floats2half2_rn(s0, s1));
}

// ---------------------------------------------------------------------------
// Main: phase A = tensor-core GEMM with f16 accumulators (m16n8k16), per-mt
// epilogue (min live regs); phase B / reduce / softmax = R14.
// ---------------------------------------------------------------------------
__global__ __launch_bounds__(TPB, 4)
void main_kernel(const float* __restrict__ x,
                 const float* __restrict__ W1,
                 const float* __restrict__ W2,
                 float* __restrict__ out) {
    __shared__ __align__(16) unsigned char smraw[SMEM_TOTAL];
    unsigned* hkb_s  = reinterpret_cast<unsigned*>(smraw + HKB_OFF);
    __half*   x_s    = reinterpret_cast<__half*>(smraw + X_OFF);
    __half*   W_s    = reinterpret_cast<__half*>(smraw + W_OFF);
    unsigned* hx_s   = reinterpret_cast<unsigned*>(smraw + HX_OFF);
    unsigned* part_s = reinterpret_cast<unsigned*>(smraw + PART_OFF);

    const int tid  = threadIdx.x;
    const int w    = tid >> 5;
    const int lane = tid & 31;
    const int sb   = blockIdx.y;
    const int tokb = blockIdx.x * TOKPB;
    const int h0   = w * 16;

    for (int i = tid; i < KK * (HH / 2); i += TPB)
        hkb_s[i] = g_hkbh[sb * KK * (HH / 2) + i];

    // Stage x as f16: x_s[tok][d], row stride XLD
    #pragma unroll
    for (int it = 0; it < 2; it++) {
        int idx = tid + it * TPB;                    // 64 tok x 8 quads
        int tok = idx >> 3, q = idx & 7;
        float4 v = *reinterpret_cast<const float4*>(
            x + ((size_t)sb * NTOK + tokb + tok) * DD + q * 4);
        unsigned* p = reinterpret_cast<unsigned*>(x_s + tok * XLD + q * 4);
        p[0] = h2bits(__floats2half2_rn(v.x, v.y));
        p[1] = h2bits(__floats2half2_rn(v.z, v.w));
    }
    // Stage Wx (rows 0..31 of W1) as f16: W_s[k][n], row stride WLD
    #pragma unroll
    for (int it = 0; it < 8; it++) {
        int idx = tid + it * TPB;                    // 2048 half2
        int k = idx >> 6, n2 = idx & 63;
        float2 wv = __ldg(reinterpret_cast<const float2*>(W1 + k * HH + n2 * 2));
        reinterpret_cast<unsigned*>(W_s + k * WLD)[n2] = h2bits(__floats2half2_rn(wv.x, wv.y));
    }
    __syncthreads();

    // ---- Phase A: mma.m16n8k16 f16 acc; per-mt epilogue ----
    {
        const unsigned xb = smem_u32(x_s);
        const unsigned wb = smem_u32(W_s);
        const int g = lane >> 2, j = lane & 3;

        // B frags for both kh, both nt (loaded once; 8 regs)
        unsigned bf[2][2][2];
        #pragma unroll
        for (int kh = 0; kh < 2; kh++)
            #pragma unroll
            for (int nt = 0; nt < 2; nt++) {
                unsigned addrB = wb + ((kh * 16 + (lane & 15)) * WLD + h0 + nt * 8) * 2;
                asm volatile("ldmatrix.sync.aligned.m8n8.x2.trans.shared.b16 {%0,%1}, [%2];"
                             : "=r"(bf[kh][nt][0]), "=r"(bf[kh][nt][1]) : "r"(addrB));
            }

        #pragma unroll
        for (int mt = 0; mt < 4; mt++) {
            unsigned d0[2] = {0u, 0u}, d1[2] = {0u, 0u};   // [nt]: rows g / g+8
            #pragma unroll
            for (int kh = 0; kh < 2; kh++) {
                int mA = mt * 16 + (lane & 7) + ((lane & 8) ? 8 : 0);
                int kA = kh * 16 + ((lane & 16) ? 8 : 0);
                unsigned addrA = xb + (mA * XLD + kA) * 2;
                unsigned a0, a1, a2, a3;
                asm volatile("ldmatrix.sync.aligned.m8n8.x4.shared.b16 {%0,%1,%2,%3}, [%4];"
                             : "=r"(a0), "=r"(a1), "=r"(a2), "=r"(a3) : "r"(addrA));
                #pragma unroll
                for (int nt = 0; nt < 2; nt++) {
                    asm volatile(
                        "mma.sync.aligned.m16n8k16.row.col.f16.f16.f16.f16 "
                        "{%0,%1}, {%2,%3,%4,%5}, {%6,%7}, {%0,%1};"
                        : "+r"(d0[nt]), "+r"(d1[nt])
                        : "r"(a0), "r"(a1), "r"(a2), "r"(a3),
                          "r"(bf[kh][nt][0]), "r"(bf[kh][nt][1]));
                }
            }
            // epilogue for this mt: d regs ARE packed half2 h-pairs
            #pragma unroll
            for (int nt = 0; nt < 2; nt++) {
                int col = nt * 4 + j;
                hx_s[(w * 64 + mt * 16 + g)     * HXP + col] = d0[nt];
                hx_s[(w * 64 + mt * 16 + g + 8) * HXP + col] = d1[nt];
            }
        }
    }
    __syncthreads();

    // Pull this thread's hx (lane's tokens, warp's h-slice) into registers
    unsigned hxh[TT][8];
    #pragma unroll
    for (int t = 0; t < TT; t++)
        #pragma unroll
        for (int q = 0; q < 8; q++)
            hxh[t][q] = hx_s[(w * 64 + t * 32 + lane) * HXP + q];
    __syncthreads();   // hx region dead; part_s overlay may be written

    // W2 slice as half2 (warp-uniform LDG)
    __half2 w2h[8];
    {
        const float4* w2p = reinterpret_cast<const float4*>(W2 + h0);
        #pragma unroll
        for (int q = 0; q < 4; q++) {
            float4 wv = __ldg(w2p + q);
            w2h[2 * q + 0] = __floats2half2_rn(wv.x, wv.y);
            w2h[2 * q + 1] = __floats2half2_rn(wv.z, wv.w);
        }
    }

    // ---- Phase B: all-f16 inner loop, half2 partial straight to smem ----
    #pragma unroll
    for (int k = 0; k < KK; k++) {
        const uint4* hkp = reinterpret_cast<const uint4*>(&hkb_s[k * (HH / 2) + w * 8]);
        uint4 hA = hkp[0], hB = hkp[1];              // warp-uniform LDS.128
        #pragma unroll
        for (int t = 0; t < TT; t++) {
            __half2 a0, a1, a2, a3;
            a0 = __hmul2(tanh2(__hadd2(asH2(hxh[t][0]), asH2(hA.x))), w2h[0]);
            a1 = __hmul2(tanh2(__hadd2(asH2(hxh[t][1]), asH2(hA.y))), w2h[1]);
            a2 = __hmul2(tanh2(__hadd2(asH2(hxh[t][2]), asH2(hA.z))), w2h[2]);
            a3 = __hmul2(tanh2(__hadd2(asH2(hxh[t][3]), asH2(hA.w))), w2h[3]);
            a0 = __hfma2(tanh2(__hadd2(asH2(hxh[t][4]), asH2(hB.x))), w2h[4], a0);
            a1 = __hfma2(tanh2(__hadd2(asH2(hxh[t][5]), asH2(hB.y))), w2h[5], a1);
            a2 = __hfma2(tanh2(__hadd2(asH2(hxh[t][6]), asH2(hB.z))), w2h[6], a2);
            a3 = __hfma2(tanh2(__hadd2(asH2(hxh[t][7]), asH2(hB.w))), w2h[7], a3);
            __half2 a = __hadd2(__hadd2(a0, a1), __hadd2(a2, a3));
            part_s[(w * 64 + t * 32 + lane) * PRT + k] = h2bits(a);
        }
    }
    __syncthreads();

    // ---- Reduce (f32) + softmax: thread = (token = tid>>2, k-quad = tid&3) ----
    const int tok = tid >> 2;
    const int kq  = tid & 3;
    float g[4];
    #pragma unroll
    for (int j = 0; j < 4; j++) {
        int k = 4 * kq + j;
        float s = 0.f;
        #pragma unroll
        for (int ww = 0; ww < NW; ww++) {
            float2 f = __half22float2(asH2(part_s[(ww * 64 + tok) * PRT + k]));
            s += f.x + f.y;
        }
        g[j] = s;
    }

    float m = fmaxf(fmaxf(g[0], g[1]), fmaxf(g[2], g[3]));
    m = fmaxf(m, __shfl_xor_sync(0xffffffffu, m, 1));
    m = fmaxf(m, __shfl_xor_sync(0xffffffffu, m, 2));

    float e0 = __expf(g[0] - m), e1 = __expf(g[1] - m);
    float e2 = __expf(g[2] - m), e3 = __expf(g[3] - m);
    float s = (e0 + e1) + (e2 + e3);
    s += __shfl_xor_sync(0xffffffffu, s, 1);
    s += __shfl_xor_sync(0xffffffffu, s, 2);
    float inv = __fdividef(1.f, s);

    float4 o;
    o.x = e0 * inv; o.y = e1 * inv; o.z = e2 * inv; o.w = e3 * inv;
    reinterpret_cast<float4*>(out + ((size_t)sb * NTOK + tokb + tok) * KK)[kq] = o;
}

extern "C" void kernel_launch(void* const* d_in, const int* in_sizes, int n_in,
                              void* d_out, int out_size) {
    const float* x   = (const float*)d_in[0];
    const float* mu  = (const float*)d_in[1];
    const float* tau = (const float*)d_in[2];
    const float* W1  = (const float*)d_in[3];
    const float* b1  = (const float*)d_in[4];
    const float* W2  = (const float*)d_in[5];
    // d_in[6] = b2: cancels in softmax, unused.
    float* out = (float*)d_out;

    prep_kernel<<<dim3(KK / 4, SB), TPB>>>(mu, tau, W1, b1);
    main_kernel<<<dim3(NTOK / TOKPB, SB), TPB>>>(x, W1, W2, out);
}